// round 15
// baseline (speedup 1.0000x reference)
#include <cuda_runtime.h>
#include <cuda_fp16.h>
#include <cstdint>

// Problem constants
#define BB   2
#define SSL  2048
#define DD   1024
#define HH   16
#define DHH  64
#define MMR  (BB*SSL)   // 4096

// Packed fp16 buffers (uint32 = 2 halves). All values fp16-rounded (rne).
// A-frag pack (m16n8k16), groups (mg=r/16, kg=d/16), NKG k-groups:
//   word(r,d) = ((mg*NKG+kg)*32 + (r&7)*4 + ((d&7)>>1))*4
//             + ((r>>3)&1) + 2*((d>>3)&1),   half = d&1
// PAIRED B-frag pack, groups (ng2=n/16, kg=k/16):
//   word(n,k) = ((ng2*NKG+kg)*32 + (n&7)*4 + ((k&7)>>1))*4
//             + ((k>>3)&1) + 2*((n>>3)&1),   half = k&1
__device__ uint32_t g_q[(size_t)BB*HH*SSL*DHH/2];    // per (b,h) A-pack (NKG=4), q*0.125*log2e
__device__ uint32_t g_k[(size_t)BB*HH*SSL*DHH/2];    // per (b,h) paired B-pack n=j,k=d (NKG=4)
__device__ uint32_t g_v[(size_t)BB*HH*SSL*DHH/2];    // per (b,h), per-64j tile: B-pack n=e,k=j_local
__device__ uint32_t g_ctxp[(size_t)MMR*DD/2];        // ctx A-pack (NKG=64)
__device__ uint32_t g_xp[(size_t)MMR*DD/2];          // x   A-pack (NKG=64)
__device__ uint32_t g_wp[(size_t)3*HH*DD*DHH/2];     // W{q,k,v} per head: B-pack n=e,k=d (NKG=64)
__device__ uint32_t g_wop[(size_t)DD*DD/2];          // Wo B-pack n,k (NKG=64)

// ---------------------------------------------------------------------------
// Helpers
// ---------------------------------------------------------------------------
__device__ __forceinline__ uint32_t fpk(float a, float b) {
    __half2 h = __floats2half2_rn(a, b);
    return *reinterpret_cast<uint32_t*>(&h);
}

__device__ __forceinline__ float ex2(float x) {
    float r;
    asm("ex2.approx.f32 %0, %1;" : "=f"(r) : "f"(x));
    return r;
}

__device__ __forceinline__ void mma_f16(float* c,
                                        uint32_t a0, uint32_t a1, uint32_t a2, uint32_t a3,
                                        uint32_t b0, uint32_t b1) {
    asm volatile(
        "mma.sync.aligned.m16n8k16.row.col.f32.f16.f16.f32 "
        "{%0,%1,%2,%3}, {%4,%5,%6,%7}, {%8,%9}, {%0,%1,%2,%3};"
        : "+f"(c[0]), "+f"(c[1]), "+f"(c[2]), "+f"(c[3])
        : "r"(a0), "r"(a1), "r"(a2), "r"(a3), "r"(b0), "r"(b1));
}

__device__ __forceinline__ uint32_t smaddr(const void* p) {
    return (uint32_t)__cvta_generic_to_shared(p);
}
#define CPA16(dst, src) \
    asm volatile("cp.async.cg.shared.global [%0], [%1], 16;" :: "r"(dst), "l"(src))
#define CPA_COMMIT() asm volatile("cp.async.commit_group;")
#define CPA_WAIT(N)  asm volatile("cp.async.wait_group %0;" :: "n"(N))

// ---------------------------------------------------------------------------
// Kernel 0: pack + fp16-round x / Wq / Wk / Wv / Wo. (unchanged)
// ---------------------------------------------------------------------------
#define XN   ((size_t)MMR*DD/4)            // 1048576
#define WTH  ((size_t)3*HH*DD*DHH/8)       // 393216
#define WOTH ((size_t)DD*DD/8)             // 131072
#define PREP_TOTAL (XN + WTH + WOTH)       // 1572864

__global__ __launch_bounds__(256) void prep_pack(
    const float* __restrict__ x,  const float* __restrict__ Wq,
    const float* __restrict__ Wk, const float* __restrict__ Wv,
    const float* __restrict__ Wo)
{
    size_t i = (size_t)blockIdx.x * 256 + threadIdx.x;
    if (i >= PREP_TOTAL) return;
    if (i < XN) {
        int r = (int)(i >> 8), d0 = ((int)i & 255) * 4;
        float4 v = ((const float4*)x)[i];
        size_t w0 = ((((size_t)(r >> 4) * 64 + (d0 >> 4)) * 32
                    + (r & 7) * 4 + ((d0 & 7) >> 1)) << 2)
                  + ((r >> 3) & 1) + 2 * ((d0 >> 3) & 1);
        g_xp[w0]     = fpk(v.x, v.y);
        g_xp[w0 + 4] = fpk(v.z, v.w);
    } else if (i < XN + WTH) {
        size_t j = i - XN;
        int z = (int)(j >> 17);
        int jr = (int)(j & 131071);
        int h = jr >> 13;
        int rem = jr & 8191;
        int k = (rem >> 4) * 2;
        int e0 = (rem & 15) * 4;
        const float* W = (z == 0) ? Wq : (z == 1) ? Wk : Wv;
        const float* p0 = W + ((size_t)h * 1024 + k) * 64 + e0;
        float4 r0 = *(const float4*)p0;
        float4 r1 = *(const float4*)(p0 + 64);
        size_t base = (size_t)(z * 16 + h) * 32768;
        size_t w0 = base
                  + ((((size_t)(e0 >> 4) * 64 + (k >> 4)) * 32
                    + (e0 & 7) * 4 + ((k & 7) >> 1)) << 2)
                  + ((k >> 3) & 1) + 2 * ((e0 >> 3) & 1);
        g_wp[w0]      = fpk(r0.x, r1.x);
        g_wp[w0 + 16] = fpk(r0.y, r1.y);
        g_wp[w0 + 32] = fpk(r0.z, r1.z);
        g_wp[w0 + 48] = fpk(r0.w, r1.w);
    } else {
        size_t j = i - XN - WTH;
        int k = (int)(j >> 8) * 2;
        int n0 = ((int)j & 255) * 4;
        const float* p0 = Wo + (size_t)k * 1024 + n0;
        float4 r0 = *(const float4*)p0;
        float4 r1 = *(const float4*)(p0 + 1024);
        size_t w0 = ((((size_t)(n0 >> 4) * 64 + (k >> 4)) * 32
                    + (n0 & 7) * 4 + ((k & 7) >> 1)) << 2)
                  + ((k >> 3) & 1) + 2 * ((n0 >> 3) & 1);
        g_wop[w0]      = fpk(r0.x, r1.x);
        g_wop[w0 + 16] = fpk(r0.y, r1.y);
        g_wop[w0 + 32] = fpk(r0.z, r1.z);
        g_wop[w0 + 48] = fpk(r0.w, r1.w);
    }
}

// ---------------------------------------------------------------------------
// GEMM core: block 128x128, BK=32, 8 warps, warp 64x32. 3-stage cp.async
// ring, one sync per iter. Fragment SOFTWARE PIPELINE: kgl0 frags + kgl1
// A-frags loaded before kgl0 mmas; kgl1 B-frags load under kgl0 mmas.
// ---------------------------------------------------------------------------
#define TW 2048
#define GEMM_SMEM_BYTES (6 * TW * 4)

// 16 mmas of one k16 step (4 m-tiles x 2 paired n-groups)
#define MMA_STEP(acc, av, bw)                                                   \
    do {                                                                        \
        _Pragma("unroll")                                                       \
        for (int n2 = 0; n2 < 2; n2++)                                          \
            _Pragma("unroll")                                                   \
            for (int mt = 0; mt < 4; mt++) {                                    \
                mma_f16(acc[mt][n2 * 2 + 0], av[mt].x, av[mt].y, av[mt].z,      \
                        av[mt].w, bw[n2].x, bw[n2].y);                          \
                mma_f16(acc[mt][n2 * 2 + 1], av[mt].x, av[mt].y, av[mt].z,      \
                        av[mt].w, bw[n2].z, bw[n2].w);                          \
            }                                                                   \
    } while (0)

// ---------------------------------------------------------------------------
// Kernel 1: fused QKV projection. grid=(8,32,3), 256 threads.
// ---------------------------------------------------------------------------
__global__ __launch_bounds__(256, 2) void qkv_kernel(
    const float* __restrict__ bq, const float* __restrict__ bk, const float* __restrict__ bv)
{
    extern __shared__ uint32_t sm[];
    const uint32_t smA = smaddr(sm);
    const uint32_t smB = smA + 3 * TW * 4;

    const int z = blockIdx.z;
    const float* __restrict__ bias = (z == 0) ? bq : (z == 1) ? bk : bv;
    uint32_t* out = (z == 0) ? g_q : (z == 1) ? g_k : g_v;
    const float scale = (z == 0) ? 0.125f * 1.4426950408889634f : 1.0f;

    const int n0 = blockIdx.x * 128;
    const int m0 = blockIdx.y * 128;
    const int hA = n0 >> 6;
    const int mg0 = m0 >> 4;

    const int tid  = threadIdx.x;
    const int lane = tid & 31;
    const int warp = tid >> 5;
    const int g = lane >> 2, t = lane & 3;
    const int wm4  = (warp >> 2) * 4;
    const int wng2 = (warp & 3) * 2;

    float acc[4][4][4];
    #pragma unroll
    for (int a = 0; a < 4; a++)
        #pragma unroll
        for (int b = 0; b < 4; b++)
            #pragma unroll
            for (int q = 0; q < 4; q++) acc[a][b][q] = 0.f;

    auto issue_tile = [&](int it2) {
        const int kg0 = it2 * 2;
        const int buf = it2 % 3;
        #pragma unroll
        for (int u = 0; u < 2; u++) {
            int c = u * 256 + tid;
            int grp = c >> 5, off = (c & 31) * 4;
            const uint32_t* src = g_xp
                + ((size_t)(mg0 + (grp >> 1)) * 64 + kg0 + (grp & 1)) * 128 + off;
            CPA16(smA + (uint32_t)(buf * TW + grp * 128 + off) * 4, src);
        }
        #pragma unroll
        for (int u = 0; u < 2; u++) {
            int c = u * 256 + tid;
            int grp = c >> 5, off = (c & 31) * 4;
            int ng2l = grp >> 1, kgl = grp & 1;
            int h = hA + (ng2l >> 2);
            const uint32_t* src = g_wp + (size_t)(z * 16 + h) * 32768
                + ((size_t)(ng2l & 3) * 64 + kg0 + kgl) * 128 + off;
            CPA16(smB + (uint32_t)(buf * TW + grp * 128 + off) * 4, src);
        }
        CPA_COMMIT();
    };

    issue_tile(0);
    issue_tile(1);

    for (int it = 0; it < 32; it++) {
        if (it == 31) { CPA_WAIT(0); } else { CPA_WAIT(1); }
        __syncthreads();
        if (it + 2 < 32) issue_tile(it + 2);

        const uint32_t* As_ = sm + (it % 3) * TW;
        const uint32_t* Bs_ = sm + 3 * TW + (it % 3) * TW;
        uint4 av0[4], av1[4], bw0[2], bw1[2];
        #pragma unroll
        for (int mt = 0; mt < 4; mt++)
            av0[mt] = *(const uint4*)&As_[((wm4 + mt) * 2 + 0) * 128 + lane * 4];
        #pragma unroll
        for (int n2 = 0; n2 < 2; n2++)
            bw0[n2] = *(const uint4*)&Bs_[((wng2 + n2) * 2 + 0) * 128 + lane * 4];
        #pragma unroll
        for (int mt = 0; mt < 4; mt++)
            av1[mt] = *(const uint4*)&As_[((wm4 + mt) * 2 + 1) * 128 + lane * 4];
        MMA_STEP(acc, av0, bw0);
        #pragma unroll
        for (int n2 = 0; n2 < 2; n2++)
            bw1[n2] = *(const uint4*)&Bs_[((wng2 + n2) * 2 + 1) * 128 + lane * 4];
        MMA_STEP(acc, av1, bw1);
    }

    // Epilogue: bias + scale + fp16-round, scatter into packed q/k/v
    const int wm0 = (warp >> 2) * 64;
    const int wn0 = (warp & 3) * 32;
    #pragma unroll
    for (int mt = 0; mt < 4; mt++) {
        #pragma unroll
        for (int nt = 0; nt < 4; nt++) {
            int cb = n0 + wn0 + (nt >> 1) * 16 + (nt & 1) * 8 + 2 * t;
            float bi0 = bias[cb], bi1 = bias[cb + 1];
            int h = cb >> 6, e0 = cb & 63;
            #pragma unroll
            for (int half = 0; half < 2; half++) {
                int m = m0 + wm0 + mt * 16 + g + half * 8;
                int b = m >> 11, s = m & (SSL - 1);
                uint32_t* plane = out + (size_t)(b * HH + h) * 65536;
                float v0 = (acc[mt][nt][half * 2 + 0] + bi0) * scale;
                float v1 = (acc[mt][nt][half * 2 + 1] + bi1) * scale;
                if (z == 0) {
                    size_t w = ((((size_t)(s >> 4) * 4 + (e0 >> 4)) * 32
                               + (s & 7) * 4 + ((e0 & 7) >> 1)) << 2)
                             + ((s >> 3) & 1) + 2 * ((e0 >> 3) & 1);
                    plane[w] = fpk(v0, v1);
                } else if (z == 1) {
                    size_t w = ((((size_t)(s >> 4) * 4 + (e0 >> 4)) * 32
                               + (s & 7) * 4 + ((e0 & 7) >> 1)) << 2)
                             + ((e0 >> 3) & 1) + 2 * ((s >> 3) & 1);
                    plane[w] = fpk(v0, v1);
                } else {
                    int sl = s & 63;
                    size_t w = (size_t)(s >> 6) * 2048
                             + ((((size_t)(e0 >> 4) * 4 + (sl >> 4)) * 32
                               + (e0 & 7) * 4 + ((sl & 7) >> 1)) << 2)
                             + ((sl >> 3) & 1) + 2 * ((e0 >> 3) & 1);
                    __half* hp = (__half*)plane;
                    hp[(w << 1) | (sl & 1)]        = __float2half_rn(v0);
                    hp[((w + 16) << 1) | (sl & 1)] = __float2half_rn(v1);
                }
            }
        }
    }
}

// ---------------------------------------------------------------------------
// Kernel 2: flash attention (unchanged from R14 — 281.6 µs pass).
// smem (words): Qs 4096 | K ring 3*2048 | V ring 3*2048 | Ps 4096 = 20480
// ---------------------------------------------------------------------------
#define QS_OFF 0
#define KR_OFF 4096
#define VR_OFF 10240
#define PS_OFF 16384
#define ATTN_SMEM_BYTES (20480 * 4)

__global__ __launch_bounds__(256, 2) void attn_kernel()
{
    extern __shared__ uint32_t sm[];

    const int tid  = threadIdx.x;
    const int lane = tid & 31;
    const int warp = tid >> 5;
    const int g = lane >> 2, t = lane & 3;

    const int bh = blockIdx.y;
    const uint32_t* __restrict__ Qg = g_q + (size_t)bh * 65536 + (size_t)blockIdx.x * 4096;
    const uint32_t* __restrict__ Kg = g_k + (size_t)bh * 65536;
    const uint32_t* __restrict__ Vg = g_v + (size_t)bh * 65536;

    const uint32_t smb = smaddr(sm);
    const int pbase = PS_OFF + warp * 512;

    auto issue_kv = [&](int i) {
        const int slot = i % 3;
        const uint32_t* Kt = Kg + (size_t)i * 2048;
        const uint32_t* Vt = Vg + (size_t)i * 2048;
        #pragma unroll
        for (int u = 0; u < 2; u++) {
            int c = u * 256 + tid;
            CPA16(smb + (uint32_t)(KR_OFF + slot * 2048 + c * 4) * 4, Kt + c * 4);
        }
        #pragma unroll
        for (int u = 0; u < 2; u++) {
            int c = u * 256 + tid;
            CPA16(smb + (uint32_t)(VR_OFF + slot * 2048 + c * 4) * 4, Vt + c * 4);
        }
        CPA_COMMIT();
    };

    #pragma unroll
    for (int u = 0; u < 4; u++) {
        int c = u * 256 + tid;
        CPA16(smb + (uint32_t)(QS_OFF + c * 4) * 4, Qg + c * 4);
    }
    {
        const int slot = 0;
        #pragma unroll
        for (int u = 0; u < 2; u++) {
            int c = u * 256 + tid;
            CPA16(smb + (uint32_t)(KR_OFF + slot * 2048 + c * 4) * 4, Kg + c * 4);
        }
        #pragma unroll
        for (int u = 0; u < 2; u++) {
            int c = u * 256 + tid;
            CPA16(smb + (uint32_t)(VR_OFF + slot * 2048 + c * 4) * 4, Vg + c * 4);
        }
        CPA_COMMIT();
    }
    issue_kv(1);

    float oacc[8][4];
    #pragma unroll
    for (int e = 0; e < 8; e++)
        #pragma unroll
        for (int q = 0; q < 4; q++) oacc[e][q] = 0.f;
    float mrun0 = -1e30f, mrun1 = -1e30f;
    float lrun0 = 0.f, lrun1 = 0.f;

    for (int i = 0; i < 32; i++) {
        if (i >= 30) { CPA_WAIT(0); } else { CPA_WAIT(1); }
        __syncthreads();
        if (i + 2 < 32) issue_kv(i + 2);

        const int ks = KR_OFF + (i % 3) * 2048;
        const int vs = VR_OFF + (i % 3) * 2048;

        float sf[8][4];
        #pragma unroll
        for (int jt = 0; jt < 8; jt++)
            #pragma unroll
            for (int q = 0; q < 4; q++) sf[jt][q] = 0.f;

        #pragma unroll
        for (int kg = 0; kg < 4; kg++) {
            uint4 aq = *(const uint4*)&sm[QS_OFF + ((warp * 4 + kg) * 32 + lane) * 4];
            #pragma unroll
            for (int jt2 = 0; jt2 < 4; jt2++) {
                uint4 kb = *(const uint4*)&sm[ks + ((jt2 * 4 + kg) * 32 + lane) * 4];
                mma_f16(sf[jt2 * 2 + 0], aq.x, aq.y, aq.z, aq.w, kb.x, kb.y);
                mma_f16(sf[jt2 * 2 + 1], aq.x, aq.y, aq.z, aq.w, kb.z, kb.w);
            }
        }

        float mx0 = -1e30f, mx1 = -1e30f;
        #pragma unroll
        for (int jt = 0; jt < 8; jt++) {
            mx0 = fmaxf(mx0, fmaxf(sf[jt][0], sf[jt][1]));
            mx1 = fmaxf(mx1, fmaxf(sf[jt][2], sf[jt][3]));
        }
        mx0 = fmaxf(mx0, __shfl_xor_sync(0xffffffffu, mx0, 1));
        mx0 = fmaxf(mx0, __shfl_xor_sync(0xffffffffu, mx0, 2));
        mx1 = fmaxf(mx1, __shfl_xor_sync(0xffffffffu, mx1, 1));
        mx1 = fmaxf(mx1, __shfl_xor_sync(0xffffffffu, mx1, 2));
        float mn0 = fmaxf(mrun0, mx0), mn1 = fmaxf(mrun1, mx1);
        float corr0 = ex2(mrun0 - mn0), corr1 = ex2(mrun1 - mn1);
        float sum0 = 0.f, sum1 = 0.f;
        #pragma unroll
        for (int jt = 0; jt < 8; jt++) {
            sf[jt][0] = ex2(sf[jt][0] - mn0);
            sf[jt][1] = ex2(sf[jt][1] - mn0);
            sf[jt][2] = ex2(sf[jt][2] - mn1);
            sf[jt][3] = ex2(sf[jt][3] - mn1);
            sum0 += sf[jt][0] + sf[jt][1];
            sum1 += sf[jt][2] + sf[jt][3];
        }
        sum0 += __shfl_xor_sync(0xffffffffu, sum0, 1);
        sum0 += __shfl_xor_sync(0xffffffffu, sum0, 2);
        sum1 += __shfl_xor_sync(0xffffffffu, sum1, 1);
        sum1 += __shfl_xor_sync(0xffffffffu, sum1, 2);
        lrun0 = lrun0 * corr0 + sum0; mrun0 = mn0;
        lrun1 = lrun1 * corr1 + sum1; mrun1 = mn1;
        #pragma unroll
        for (int e = 0; e < 8; e++) {
            oacc[e][0] *= corr0; oacc[e][1] *= corr0;
            oacc[e][2] *= corr1; oacc[e][3] *= corr1;
        }

        #pragma unroll
        for (int kg = 0; kg < 4; kg++) {
            uint4 pw;
            pw.x = fpk(sf[2 * kg][0],     sf[2 * kg][1]);
            pw.y = fpk(sf[2 * kg][2],     sf[2 * kg][3]);
            pw.z = fpk(sf[2 * kg + 1][0], sf[2 * kg + 1][1]);
            pw.w = fpk(sf[2 * kg + 1][2], sf[2 * kg + 1][3]);
            *(uint4*)&sm[pbase + (kg * 32 + lane) * 4] = pw;
        }
        __syncwarp();

        #pragma unroll
        for (int kg = 0; kg < 4; kg++) {
            uint4 pa = *(const uint4*)&sm[pbase + (kg * 32 + lane) * 4];
            #pragma unroll
            for (int et2 = 0; et2 < 4; et2++) {
                uint4 vb = *(const uint4*)&sm[vs + ((et2 * 4 + kg) * 32 + lane) * 4];
                mma_f16(oacc[et2 * 2 + 0], pa.x, pa.y, pa.z, pa.w, vb.x, vb.y);
                mma_f16(oacc[et2 * 2 + 1], pa.x, pa.y, pa.z, pa.w, vb.z, vb.w);
            }
        }
    }

    const int b = bh >> 4, h = bh & 15;
    const int m0 = blockIdx.x * 128;
    const float inv0 = 1.f / lrun0, inv1 = 1.f / lrun1;
    const int row0 = m0 + warp * 16 + g;
    const int mrow = (b << 11) + row0;
    #pragma unroll
    for (int et = 0; et < 8; et++) {
        int d = h * DHH + et * 8 + 2 * t;
        size_t w = ((((size_t)(mrow >> 4) * 64 + (d >> 4)) * 32
                   + (mrow & 7) * 4 + ((d & 7) >> 1)) << 2)
                 + 2 * ((d >> 3) & 1);
        g_ctxp[w]     = fpk(oacc[et][0] * inv0, oacc[et][1] * inv0);
        g_ctxp[w + 1] = fpk(oacc[et][2] * inv1, oacc[et][3] * inv1);
    }
}

// ---------------------------------------------------------------------------
// Kernel 3: output projection. Same fragment pipeline. grid=(8,32), 256 thr.
// ---------------------------------------------------------------------------
__global__ __launch_bounds__(256, 2) void proj_kernel(
    const float* __restrict__ bo, float* __restrict__ out)
{
    extern __shared__ uint32_t sm[];
    const uint32_t smA = smaddr(sm);
    const uint32_t smB = smA + 3 * TW * 4;

    const int n0 = blockIdx.x * 128;
    const int m0 = blockIdx.y * 128;
    const int mg0 = m0 >> 4;
    const int ng20 = n0 >> 4;

    const int tid  = threadIdx.x;
    const int lane = tid & 31;
    const int warp = tid >> 5;
    const int g = lane >> 2, t = lane & 3;
    const int wm4  = (warp >> 2) * 4;
    const int wng2 = (warp & 3) * 2;

    float acc[4][4][4];
    #pragma unroll
    for (int a = 0; a < 4; a++)
        #pragma unroll
        for (int b = 0; b < 4; b++)
            #pragma unroll
            for (int q = 0; q < 4; q++) acc[a][b][q] = 0.f;

    auto issue_tile = [&](int it2) {
        const int kg0 = it2 * 2;
        const int buf = it2 % 3;
        #pragma unroll
        for (int u = 0; u < 2; u++) {
            int c = u * 256 + tid;
            int grp = c >> 5, off = (c & 31) * 4;
            const uint32_t* src = g_ctxp
                + ((size_t)(mg0 + (grp >> 1)) * 64 + kg0 + (grp & 1)) * 128 + off;
            CPA16(smA + (uint32_t)(buf * TW + grp * 128 + off) * 4, src);
        }
        #pragma unroll
        for (int u = 0; u < 2; u++) {
            int c = u * 256 + tid;
            int grp = c >> 5, off = (c & 31) * 4;
            const uint32_t* src = g_wop
                + ((size_t)(ng20 + (grp >> 1)) * 64 + kg0 + (grp & 1)) * 128 + off;
            CPA16(smB + (uint32_t)(buf * TW + grp * 128 + off) * 4, src);
        }
        CPA_COMMIT();
    };

    issue_tile(0);
    issue_tile(1);

    for (int it = 0; it < 32; it++) {
        if (it == 31) { CPA_WAIT(0); } else { CPA_WAIT(1); }
        __syncthreads();
        if (it + 2 < 32) issue_tile(it + 2);

        const uint32_t* As_ = sm + (it % 3) * TW;
        const uint32_t* Bs_ = sm + 3 * TW + (it % 3) * TW;
        uint4 av0[4], av1[4], bw0[2], bw1[2];
        #pragma unroll
        for (int mt = 0; mt < 4; mt++)
            av0[mt] = *(const uint4*)&As_[((wm4 + mt) * 2 + 0) * 128 + lane * 4];
        #pragma unroll
        for (int n2 = 0; n2 < 2; n2++)
            bw0[n2] = *(const uint4*)&Bs_[((wng2 + n2) * 2 + 0) * 128 + lane * 4];
        #pragma unroll
        for (int mt = 0; mt < 4; mt++)
            av1[mt] = *(const uint4*)&As_[((wm4 + mt) * 2 + 1) * 128 + lane * 4];
        MMA_STEP(acc, av0, bw0);
        #pragma unroll
        for (int n2 = 0; n2 < 2; n2++)
            bw1[n2] = *(const uint4*)&Bs_[((wng2 + n2) * 2 + 1) * 128 + lane * 4];
        MMA_STEP(acc, av1, bw1);
    }

    const int wm0 = (warp >> 2) * 64;
    const int wn0 = (warp & 3) * 32;
    #pragma unroll
    for (int mt = 0; mt < 4; mt++) {
        #pragma unroll
        for (int nt = 0; nt < 4; nt++) {
            int cb = n0 + wn0 + (nt >> 1) * 16 + (nt & 1) * 8 + 2 * t;
            float bi0 = bo[cb], bi1 = bo[cb + 1];
            #pragma unroll
            for (int half = 0; half < 2; half++) {
                int m = m0 + wm0 + mt * 16 + g + half * 8;
                float2 o = make_float2(acc[mt][nt][half * 2 + 0] + bi0,
                                       acc[mt][nt][half * 2 + 1] + bi1);
                *(float2*)&out[(size_t)m * DD + cb] = o;
            }
        }
    }
}

// ---------------------------------------------------------------------------
extern "C" void kernel_launch(void* const* d_in, const int* in_sizes, int n_in,
                              void* d_out, int out_size)
{
    (void)in_sizes; (void)n_in; (void)out_size;
    const float* x  = (const float*)d_in[0];
    const float* Wq = (const float*)d_in[1];
    const float* Wk = (const float*)d_in[2];
    const float* Wv = (const float*)d_in[3];
    const float* bq = (const float*)d_in[4];
    const float* bk = (const float*)d_in[5];
    const float* bv = (const float*)d_in[6];
    const float* Wo = (const float*)d_in[7];
    const float* bo = (const float*)d_in[8];
    float* out = (float*)d_out;

    cudaFuncSetAttribute(qkv_kernel,  cudaFuncAttributeMaxDynamicSharedMemorySize, GEMM_SMEM_BYTES);
    cudaFuncSetAttribute(proj_kernel, cudaFuncAttributeMaxDynamicSharedMemorySize, GEMM_SMEM_BYTES);
    cudaFuncSetAttribute(attn_kernel, cudaFuncAttributeMaxDynamicSharedMemorySize, ATTN_SMEM_BYTES);

    prep_pack<<<(unsigned)((PREP_TOTAL + 255) / 256), 256>>>(x, Wq, Wk, Wv, Wo);
    qkv_kernel<<<dim3(8, 32, 3), 256, GEMM_SMEM_BYTES>>>(bq, bk, bv);
    attn_kernel<<<dim3(16, 32), 256, ATTN_SMEM_BYTES>>>();
    proj_kernel<<<dim3(8, 32), 256, GEMM_SMEM_BYTES>>>(bo, out);
}

// round 16
// speedup vs baseline: 1.0775x; 1.0775x over previous
#include <cuda_runtime.h>
#include <cuda_fp16.h>
#include <cstdint>

// Problem constants
#define BB   2
#define SSL  2048
#define DD   1024
#define HH   16
#define DHH  64
#define MMR  (BB*SSL)   // 4096

// Packed fp16 buffers (uint32 = 2 halves). All values fp16-rounded (rne).
// A-frag pack (m16n8k16), groups (mg=r/16, kg=d/16), NKG k-groups:
//   word(r,d) = ((mg*NKG+kg)*32 + (r&7)*4 + ((d&7)>>1))*4
//             + ((r>>3)&1) + 2*((d>>3)&1),   half = d&1
// PAIRED B-frag pack, groups (ng2=n/16, kg=k/16):
//   word(n,k) = ((ng2*NKG+kg)*32 + (n&7)*4 + ((k&7)>>1))*4
//             + ((k>>3)&1) + 2*((n>>3)&1),   half = k&1
__device__ uint32_t g_q[(size_t)BB*HH*SSL*DHH/2];    // per (b,h) A-pack (NKG=4), q*0.125*log2e
__device__ uint32_t g_k[(size_t)BB*HH*SSL*DHH/2];    // per (b,h) paired B-pack n=j,k=d (NKG=4)
__device__ uint32_t g_v[(size_t)BB*HH*SSL*DHH/2];    // per (b,h), per-64j tile: B-pack n=e,k=j_local
__device__ uint32_t g_ctxp[(size_t)MMR*DD/2];        // ctx A-pack (NKG=64)
__device__ uint32_t g_xp[(size_t)MMR*DD/2];          // x   A-pack (NKG=64)
__device__ uint32_t g_wp[(size_t)3*HH*DD*DHH/2];     // W{q,k,v} per head: B-pack n=e,k=d (NKG=64)
__device__ uint32_t g_wop[(size_t)DD*DD/2];          // Wo B-pack n,k (NKG=64)

// ---------------------------------------------------------------------------
// Helpers
// ---------------------------------------------------------------------------
__device__ __forceinline__ uint32_t fpk(float a, float b) {
    __half2 h = __floats2half2_rn(a, b);
    return *reinterpret_cast<uint32_t*>(&h);
}

__device__ __forceinline__ float ex2(float x) {
    float r;
    asm("ex2.approx.f32 %0, %1;" : "=f"(r) : "f"(x));
    return r;
}

__device__ __forceinline__ void mma_f16(float* c,
                                        uint32_t a0, uint32_t a1, uint32_t a2, uint32_t a3,
                                        uint32_t b0, uint32_t b1) {
    asm volatile(
        "mma.sync.aligned.m16n8k16.row.col.f32.f16.f16.f32 "
        "{%0,%1,%2,%3}, {%4,%5,%6,%7}, {%8,%9}, {%0,%1,%2,%3};"
        : "+f"(c[0]), "+f"(c[1]), "+f"(c[2]), "+f"(c[3])
        : "r"(a0), "r"(a1), "r"(a2), "r"(a3), "r"(b0), "r"(b1));
}

__device__ __forceinline__ uint32_t smaddr(const void* p) {
    return (uint32_t)__cvta_generic_to_shared(p);
}
#define CPA16(dst, src) \
    asm volatile("cp.async.cg.shared.global [%0], [%1], 16;" :: "r"(dst), "l"(src))
#define CPA_COMMIT() asm volatile("cp.async.commit_group;")
#define CPA_WAIT(N)  asm volatile("cp.async.wait_group %0;" :: "n"(N))

// ---------------------------------------------------------------------------
// Kernel 0: pack + fp16-round x / Wq / Wk / Wv / Wo. (unchanged)
// ---------------------------------------------------------------------------
#define XN   ((size_t)MMR*DD/4)            // 1048576
#define WTH  ((size_t)3*HH*DD*DHH/8)       // 393216
#define WOTH ((size_t)DD*DD/8)             // 131072
#define PREP_TOTAL (XN + WTH + WOTH)       // 1572864

__global__ __launch_bounds__(256) void prep_pack(
    const float* __restrict__ x,  const float* __restrict__ Wq,
    const float* __restrict__ Wk, const float* __restrict__ Wv,
    const float* __restrict__ Wo)
{
    size_t i = (size_t)blockIdx.x * 256 + threadIdx.x;
    if (i >= PREP_TOTAL) return;
    if (i < XN) {
        int r = (int)(i >> 8), d0 = ((int)i & 255) * 4;
        float4 v = ((const float4*)x)[i];
        size_t w0 = ((((size_t)(r >> 4) * 64 + (d0 >> 4)) * 32
                    + (r & 7) * 4 + ((d0 & 7) >> 1)) << 2)
                  + ((r >> 3) & 1) + 2 * ((d0 >> 3) & 1);
        g_xp[w0]     = fpk(v.x, v.y);
        g_xp[w0 + 4] = fpk(v.z, v.w);
    } else if (i < XN + WTH) {
        size_t j = i - XN;
        int z = (int)(j >> 17);
        int jr = (int)(j & 131071);
        int h = jr >> 13;
        int rem = jr & 8191;
        int k = (rem >> 4) * 2;
        int e0 = (rem & 15) * 4;
        const float* W = (z == 0) ? Wq : (z == 1) ? Wk : Wv;
        const float* p0 = W + ((size_t)h * 1024 + k) * 64 + e0;
        float4 r0 = *(const float4*)p0;
        float4 r1 = *(const float4*)(p0 + 64);
        size_t base = (size_t)(z * 16 + h) * 32768;
        size_t w0 = base
                  + ((((size_t)(e0 >> 4) * 64 + (k >> 4)) * 32
                    + (e0 & 7) * 4 + ((k & 7) >> 1)) << 2)
                  + ((k >> 3) & 1) + 2 * ((e0 >> 3) & 1);
        g_wp[w0]      = fpk(r0.x, r1.x);
        g_wp[w0 + 16] = fpk(r0.y, r1.y);
        g_wp[w0 + 32] = fpk(r0.z, r1.z);
        g_wp[w0 + 48] = fpk(r0.w, r1.w);
    } else {
        size_t j = i - XN - WTH;
        int k = (int)(j >> 8) * 2;
        int n0 = ((int)j & 255) * 4;
        const float* p0 = Wo + (size_t)k * 1024 + n0;
        float4 r0 = *(const float4*)p0;
        float4 r1 = *(const float4*)(p0 + 1024);
        size_t w0 = ((((size_t)(n0 >> 4) * 64 + (k >> 4)) * 32
                    + (n0 & 7) * 4 + ((k & 7) >> 1)) << 2)
                  + ((k >> 3) & 1) + 2 * ((n0 >> 3) & 1);
        g_wop[w0]      = fpk(r0.x, r1.x);
        g_wop[w0 + 16] = fpk(r0.y, r1.y);
        g_wop[w0 + 32] = fpk(r0.z, r1.z);
        g_wop[w0 + 48] = fpk(r0.w, r1.w);
    }
}

// ---------------------------------------------------------------------------
// GEMM core (R14 form): block 128x128, BK=32, 8 warps, warp 64x32.
// 3-stage cp.async ring, one sync per iter. smem 48KB.
// ---------------------------------------------------------------------------
#define TW 2048
#define GEMM_SMEM_BYTES (6 * TW * 4)

// ---------------------------------------------------------------------------
// Kernel 1: fused QKV projection. grid=(8,32,3), 256 threads.
// ---------------------------------------------------------------------------
__global__ __launch_bounds__(256, 2) void qkv_kernel(
    const float* __restrict__ bq, const float* __restrict__ bk, const float* __restrict__ bv)
{
    extern __shared__ uint32_t sm[];
    const uint32_t smA = smaddr(sm);
    const uint32_t smB = smA + 3 * TW * 4;

    const int z = blockIdx.z;
    const float* __restrict__ bias = (z == 0) ? bq : (z == 1) ? bk : bv;
    uint32_t* out = (z == 0) ? g_q : (z == 1) ? g_k : g_v;
    const float scale = (z == 0) ? 0.125f * 1.4426950408889634f : 1.0f;

    const int n0 = blockIdx.x * 128;
    const int m0 = blockIdx.y * 128;
    const int hA = n0 >> 6;
    const int mg0 = m0 >> 4;

    const int tid  = threadIdx.x;
    const int lane = tid & 31;
    const int warp = tid >> 5;
    const int g = lane >> 2, t = lane & 3;
    const int wm4  = (warp >> 2) * 4;
    const int wng2 = (warp & 3) * 2;

    float acc[4][4][4];
    #pragma unroll
    for (int a = 0; a < 4; a++)
        #pragma unroll
        for (int b = 0; b < 4; b++)
            #pragma unroll
            for (int q = 0; q < 4; q++) acc[a][b][q] = 0.f;

    auto issue_tile = [&](int it2) {
        const int kg0 = it2 * 2;
        const int buf = it2 % 3;
        #pragma unroll
        for (int u = 0; u < 2; u++) {
            int c = u * 256 + tid;
            int grp = c >> 5, off = (c & 31) * 4;
            const uint32_t* src = g_xp
                + ((size_t)(mg0 + (grp >> 1)) * 64 + kg0 + (grp & 1)) * 128 + off;
            CPA16(smA + (uint32_t)(buf * TW + grp * 128 + off) * 4, src);
        }
        #pragma unroll
        for (int u = 0; u < 2; u++) {
            int c = u * 256 + tid;
            int grp = c >> 5, off = (c & 31) * 4;
            int ng2l = grp >> 1, kgl = grp & 1;
            int h = hA + (ng2l >> 2);
            const uint32_t* src = g_wp + (size_t)(z * 16 + h) * 32768
                + ((size_t)(ng2l & 3) * 64 + kg0 + kgl) * 128 + off;
            CPA16(smB + (uint32_t)(buf * TW + grp * 128 + off) * 4, src);
        }
        CPA_COMMIT();
    };

    issue_tile(0);
    issue_tile(1);

    for (int it = 0; it < 32; it++) {
        if (it == 31) { CPA_WAIT(0); } else { CPA_WAIT(1); }
        __syncthreads();
        if (it + 2 < 32) issue_tile(it + 2);

        const uint32_t* As_ = sm + (it % 3) * TW;
        const uint32_t* Bs_ = sm + 3 * TW + (it % 3) * TW;
        #pragma unroll
        for (int kgl = 0; kgl < 2; kgl++) {
            uint4 av[4], bw[2];
            #pragma unroll
            for (int mt = 0; mt < 4; mt++)
                av[mt] = *(const uint4*)&As_[((wm4 + mt) * 2 + kgl) * 128 + lane * 4];
            #pragma unroll
            for (int n2 = 0; n2 < 2; n2++)
                bw[n2] = *(const uint4*)&Bs_[((wng2 + n2) * 2 + kgl) * 128 + lane * 4];
            #pragma unroll
            for (int n2 = 0; n2 < 2; n2++)
                #pragma unroll
                for (int mt = 0; mt < 4; mt++) {
                    mma_f16(acc[mt][n2 * 2 + 0], av[mt].x, av[mt].y, av[mt].z, av[mt].w,
                            bw[n2].x, bw[n2].y);
                    mma_f16(acc[mt][n2 * 2 + 1], av[mt].x, av[mt].y, av[mt].z, av[mt].w,
                            bw[n2].z, bw[n2].w);
                }
        }
    }

    // Epilogue: bias + scale + fp16-round, scatter into packed q/k/v
    const int wm0 = (warp >> 2) * 64;
    const int wn0 = (warp & 3) * 32;
    #pragma unroll
    for (int mt = 0; mt < 4; mt++) {
        #pragma unroll
        for (int nt = 0; nt < 4; nt++) {
            int cb = n0 + wn0 + (nt >> 1) * 16 + (nt & 1) * 8 + 2 * t;
            float bi0 = bias[cb], bi1 = bias[cb + 1];
            int h = cb >> 6, e0 = cb & 63;
            #pragma unroll
            for (int half = 0; half < 2; half++) {
                int m = m0 + wm0 + mt * 16 + g + half * 8;
                int b = m >> 11, s = m & (SSL - 1);
                uint32_t* plane = out + (size_t)(b * HH + h) * 65536;
                float v0 = (acc[mt][nt][half * 2 + 0] + bi0) * scale;
                float v1 = (acc[mt][nt][half * 2 + 1] + bi1) * scale;
                if (z == 0) {
                    size_t w = ((((size_t)(s >> 4) * 4 + (e0 >> 4)) * 32
                               + (s & 7) * 4 + ((e0 & 7) >> 1)) << 2)
                             + ((s >> 3) & 1) + 2 * ((e0 >> 3) & 1);
                    plane[w] = fpk(v0, v1);
                } else if (z == 1) {
                    size_t w = ((((size_t)(s >> 4) * 4 + (e0 >> 4)) * 32
                               + (s & 7) * 4 + ((e0 & 7) >> 1)) << 2)
                             + ((e0 >> 3) & 1) + 2 * ((s >> 3) & 1);
                    plane[w] = fpk(v0, v1);
                } else {
                    int sl = s & 63;
                    size_t w = (size_t)(s >> 6) * 2048
                             + ((((size_t)(e0 >> 4) * 4 + (sl >> 4)) * 32
                               + (e0 & 7) * 4 + ((sl & 7) >> 1)) << 2)
                             + ((sl >> 3) & 1) + 2 * ((e0 >> 3) & 1);
                    __half* hp = (__half*)plane;
                    hp[(w << 1) | (sl & 1)]        = __float2half_rn(v0);
                    hp[((w + 16) << 1) | (sl & 1)] = __float2half_rn(v1);
                }
            }
        }
    }
}

// ---------------------------------------------------------------------------
// Kernel 2: flash attention. P stays in REGISTERS (QK c-frag -> PV A-frag is
// thread-local for m16n8k16) — no smem round trip, no syncwarp.
// 3-deep K/V ring, one barrier per kv-tile. q-tile 128, kv-tile 64.
// smem (words): Qs 4096 | K ring 3*2048 | V ring 3*2048 = 16384 -> 64KB.
// ---------------------------------------------------------------------------
#define QS_OFF 0
#define KR_OFF 4096
#define VR_OFF 10240
#define ATTN_SMEM_BYTES (16384 * 4)

__global__ __launch_bounds__(256, 2) void attn_kernel()
{
    extern __shared__ uint32_t sm[];

    const int tid  = threadIdx.x;
    const int lane = tid & 31;
    const int warp = tid >> 5;
    const int g = lane >> 2, t = lane & 3;

    const int bh = blockIdx.y;
    const uint32_t* __restrict__ Qg = g_q + (size_t)bh * 65536 + (size_t)blockIdx.x * 4096;
    const uint32_t* __restrict__ Kg = g_k + (size_t)bh * 65536;
    const uint32_t* __restrict__ Vg = g_v + (size_t)bh * 65536;

    const uint32_t smb = smaddr(sm);

    auto issue_kv = [&](int i) {
        const int slot = i % 3;
        const uint32_t* Kt = Kg + (size_t)i * 2048;
        const uint32_t* Vt = Vg + (size_t)i * 2048;
        #pragma unroll
        for (int u = 0; u < 2; u++) {
            int c = u * 256 + tid;
            CPA16(smb + (uint32_t)(KR_OFF + slot * 2048 + c * 4) * 4, Kt + c * 4);
        }
        #pragma unroll
        for (int u = 0; u < 2; u++) {
            int c = u * 256 + tid;
            CPA16(smb + (uint32_t)(VR_OFF + slot * 2048 + c * 4) * 4, Vt + c * 4);
        }
        CPA_COMMIT();
    };

    // Prologue: {Q, K0, V0} then {K1, V1}
    #pragma unroll
    for (int u = 0; u < 4; u++) {
        int c = u * 256 + tid;
        CPA16(smb + (uint32_t)(QS_OFF + c * 4) * 4, Qg + c * 4);
    }
    {
        #pragma unroll
        for (int u = 0; u < 2; u++) {
            int c = u * 256 + tid;
            CPA16(smb + (uint32_t)(KR_OFF + c * 4) * 4, Kg + c * 4);
        }
        #pragma unroll
        for (int u = 0; u < 2; u++) {
            int c = u * 256 + tid;
            CPA16(smb + (uint32_t)(VR_OFF + c * 4) * 4, Vg + c * 4);
        }
        CPA_COMMIT();
    }
    issue_kv(1);

    float oacc[8][4];
    #pragma unroll
    for (int e = 0; e < 8; e++)
        #pragma unroll
        for (int q = 0; q < 4; q++) oacc[e][q] = 0.f;
    float mrun0 = -1e30f, mrun1 = -1e30f;
    float lrun0 = 0.f, lrun1 = 0.f;

    for (int i = 0; i < 32; i++) {
        if (i >= 30) { CPA_WAIT(0); } else { CPA_WAIT(1); }
        __syncthreads();        // tile i visible; slot (i+2)%3 free
        if (i + 2 < 32) issue_kv(i + 2);

        const int ks = KR_OFF + (i % 3) * 2048;
        const int vs = VR_OFF + (i % 3) * 2048;

        // S = Q K^T
        float sf[8][4];
        #pragma unroll
        for (int jt = 0; jt < 8; jt++)
            #pragma unroll
            for (int q = 0; q < 4; q++) sf[jt][q] = 0.f;

        #pragma unroll
        for (int kg = 0; kg < 4; kg++) {
            uint4 aq = *(const uint4*)&sm[QS_OFF + ((warp * 4 + kg) * 32 + lane) * 4];
            #pragma unroll
            for (int jt2 = 0; jt2 < 4; jt2++) {
                uint4 kb = *(const uint4*)&sm[ks + ((jt2 * 4 + kg) * 32 + lane) * 4];
                mma_f16(sf[jt2 * 2 + 0], aq.x, aq.y, aq.z, aq.w, kb.x, kb.y);
                mma_f16(sf[jt2 * 2 + 1], aq.x, aq.y, aq.z, aq.w, kb.z, kb.w);
            }
        }

        // Online softmax in base-2
        float mx0 = -1e30f, mx1 = -1e30f;
        #pragma unroll
        for (int jt = 0; jt < 8; jt++) {
            mx0 = fmaxf(mx0, fmaxf(sf[jt][0], sf[jt][1]));
            mx1 = fmaxf(mx1, fmaxf(sf[jt][2], sf[jt][3]));
        }
        mx0 = fmaxf(mx0, __shfl_xor_sync(0xffffffffu, mx0, 1));
        mx0 = fmaxf(mx0, __shfl_xor_sync(0xffffffffu, mx0, 2));
        mx1 = fmaxf(mx1, __shfl_xor_sync(0xffffffffu, mx1, 1));
        mx1 = fmaxf(mx1, __shfl_xor_sync(0xffffffffu, mx1, 2));
        float mn0 = fmaxf(mrun0, mx0), mn1 = fmaxf(mrun1, mx1);
        float corr0 = ex2(mrun0 - mn0), corr1 = ex2(mrun1 - mn1);
        float sum0 = 0.f, sum1 = 0.f;
        #pragma unroll
        for (int jt = 0; jt < 8; jt++) {
            sf[jt][0] = ex2(sf[jt][0] - mn0);
            sf[jt][1] = ex2(sf[jt][1] - mn0);
            sf[jt][2] = ex2(sf[jt][2] - mn1);
            sf[jt][3] = ex2(sf[jt][3] - mn1);
            sum0 += sf[jt][0] + sf[jt][1];
            sum1 += sf[jt][2] + sf[jt][3];
        }
        sum0 += __shfl_xor_sync(0xffffffffu, sum0, 1);
        sum0 += __shfl_xor_sync(0xffffffffu, sum0, 2);
        sum1 += __shfl_xor_sync(0xffffffffu, sum1, 1);
        sum1 += __shfl_xor_sync(0xffffffffu, sum1, 2);
        lrun0 = lrun0 * corr0 + sum0; mrun0 = mn0;
        lrun1 = lrun1 * corr1 + sum1; mrun1 = mn1;
        #pragma unroll
        for (int e = 0; e < 8; e++) {
            oacc[e][0] *= corr0; oacc[e][1] *= corr0;
            oacc[e][2] *= corr1; oacc[e][3] *= corr1;
        }

        // O += P V : P built directly in registers (A-frag == packed c-frags)
        #pragma unroll
        for (int kg = 0; kg < 4; kg++) {
            uint4 pa;
            pa.x = fpk(sf[2 * kg][0],     sf[2 * kg][1]);       // P[g][16kg+2t..]
            pa.y = fpk(sf[2 * kg][2],     sf[2 * kg][3]);       // P[g+8][16kg+2t..]
            pa.z = fpk(sf[2 * kg + 1][0], sf[2 * kg + 1][1]);   // P[g][16kg+8+2t..]
            pa.w = fpk(sf[2 * kg + 1][2], sf[2 * kg + 1][3]);   // P[g+8][16kg+8+2t..]
            #pragma unroll
            for (int et2 = 0; et2 < 4; et2++) {
                uint4 vb = *(const uint4*)&sm[vs + ((et2 * 4 + kg) * 32 + lane) * 4];
                mma_f16(oacc[et2 * 2 + 0], pa.x, pa.y, pa.z, pa.w, vb.x, vb.y);
                mma_f16(oacc[et2 * 2 + 1], pa.x, pa.y, pa.z, pa.w, vb.z, vb.w);
            }
        }
    }

    // Epilogue: normalize, fp16-round, write ctx in A-frag pack
    const int b = bh >> 4, h = bh & 15;
    const int m0 = blockIdx.x * 128;
    const float inv0 = 1.f / lrun0, inv1 = 1.f / lrun1;
    const int row0 = m0 + warp * 16 + g;
    const int mrow = (b << 11) + row0;
    #pragma unroll
    for (int et = 0; et < 8; et++) {
        int d = h * DHH + et * 8 + 2 * t;
        size_t w = ((((size_t)(mrow >> 4) * 64 + (d >> 4)) * 32
                   + (mrow & 7) * 4 + ((d & 7) >> 1)) << 2)
                 + 2 * ((d >> 3) & 1);
        g_ctxp[w]     = fpk(oacc[et][0] * inv0, oacc[et][1] * inv0);   // rows g
        g_ctxp[w + 1] = fpk(oacc[et][2] * inv1, oacc[et][3] * inv1);   // rows g+8
    }
}

// ---------------------------------------------------------------------------
// Kernel 3: output projection (R14 form). grid=(8,32), 256 thr.
// ---------------------------------------------------------------------------
__global__ __launch_bounds__(256, 2) void proj_kernel(
    const float* __restrict__ bo, float* __restrict__ out)
{
    extern __shared__ uint32_t sm[];
    const uint32_t smA = smaddr(sm);
    const uint32_t smB = smA + 3 * TW * 4;

    const int n0 = blockIdx.x * 128;
    const int m0 = blockIdx.y * 128;
    const int mg0 = m0 >> 4;
    const int ng20 = n0 >> 4;

    const int tid  = threadIdx.x;
    const int lane = tid & 31;
    const int warp = tid >> 5;
    const int g = lane >> 2, t = lane & 3;
    const int wm4  = (warp >> 2) * 4;
    const int wng2 = (warp & 3) * 2;

    float acc[4][4][4];
    #pragma unroll
    for (int a = 0; a < 4; a++)
        #pragma unroll
        for (int b = 0; b < 4; b++)
            #pragma unroll
            for (int q = 0; q < 4; q++) acc[a][b][q] = 0.f;

    auto issue_tile = [&](int it2) {
        const int kg0 = it2 * 2;
        const int buf = it2 % 3;
        #pragma unroll
        for (int u = 0; u < 2; u++) {
            int c = u * 256 + tid;
            int grp = c >> 5, off = (c & 31) * 4;
            const uint32_t* src = g_ctxp
                + ((size_t)(mg0 + (grp >> 1)) * 64 + kg0 + (grp & 1)) * 128 + off;
            CPA16(smA + (uint32_t)(buf * TW + grp * 128 + off) * 4, src);
        }
        #pragma unroll
        for (int u = 0; u < 2; u++) {
            int c = u * 256 + tid;
            int grp = c >> 5, off = (c & 31) * 4;
            const uint32_t* src = g_wop
                + ((size_t)(ng20 + (grp >> 1)) * 64 + kg0 + (grp & 1)) * 128 + off;
            CPA16(smB + (uint32_t)(buf * TW + grp * 128 + off) * 4, src);
        }
        CPA_COMMIT();
    };

    issue_tile(0);
    issue_tile(1);

    for (int it = 0; it < 32; it++) {
        if (it == 31) { CPA_WAIT(0); } else { CPA_WAIT(1); }
        __syncthreads();
        if (it + 2 < 32) issue_tile(it + 2);

        const uint32_t* As_ = sm + (it % 3) * TW;
        const uint32_t* Bs_ = sm + 3 * TW + (it % 3) * TW;
        #pragma unroll
        for (int kgl = 0; kgl < 2; kgl++) {
            uint4 av[4], bw[2];
            #pragma unroll
            for (int mt = 0; mt < 4; mt++)
                av[mt] = *(const uint4*)&As_[((wm4 + mt) * 2 + kgl) * 128 + lane * 4];
            #pragma unroll
            for (int n2 = 0; n2 < 2; n2++)
                bw[n2] = *(const uint4*)&Bs_[((wng2 + n2) * 2 + kgl) * 128 + lane * 4];
            #pragma unroll
            for (int n2 = 0; n2 < 2; n2++)
                #pragma unroll
                for (int mt = 0; mt < 4; mt++) {
                    mma_f16(acc[mt][n2 * 2 + 0], av[mt].x, av[mt].y, av[mt].z, av[mt].w,
                            bw[n2].x, bw[n2].y);
                    mma_f16(acc[mt][n2 * 2 + 1], av[mt].x, av[mt].y, av[mt].z, av[mt].w,
                            bw[n2].z, bw[n2].w);
                }
        }
    }

    const int wm0 = (warp >> 2) * 64;
    const int wn0 = (warp & 3) * 32;
    #pragma unroll
    for (int mt = 0; mt < 4; mt++) {
        #pragma unroll
        for (int nt = 0; nt < 4; nt++) {
            int cb = n0 + wn0 + (nt >> 1) * 16 + (nt & 1) * 8 + 2 * t;
            float bi0 = bo[cb], bi1 = bo[cb + 1];
            #pragma unroll
            for (int half = 0; half < 2; half++) {
                int m = m0 + wm0 + mt * 16 + g + half * 8;
                float2 o = make_float2(acc[mt][nt][half * 2 + 0] + bi0,
                                       acc[mt][nt][half * 2 + 1] + bi1);
                *(float2*)&out[(size_t)m * DD + cb] = o;
            }
        }
    }
}

// ---------------------------------------------------------------------------
extern "C" void kernel_launch(void* const* d_in, const int* in_sizes, int n_in,
                              void* d_out, int out_size)
{
    (void)in_sizes; (void)n_in; (void)out_size;
    const float* x  = (const float*)d_in[0];
    const float* Wq = (const float*)d_in[1];
    const float* Wk = (const float*)d_in[2];
    const float* Wv = (const float*)d_in[3];
    const float* bq = (const float*)d_in[4];
    const float* bk = (const float*)d_in[5];
    const float* bv = (const float*)d_in[6];
    const float* Wo = (const float*)d_in[7];
    const float* bo = (const float*)d_in[8];
    float* out = (float*)d_out;

    cudaFuncSetAttribute(qkv_kernel,  cudaFuncAttributeMaxDynamicSharedMemorySize, GEMM_SMEM_BYTES);
    cudaFuncSetAttribute(proj_kernel, cudaFuncAttributeMaxDynamicSharedMemorySize, GEMM_SMEM_BYTES);
    cudaFuncSetAttribute(attn_kernel, cudaFuncAttributeMaxDynamicSharedMemorySize, ATTN_SMEM_BYTES);

    prep_pack<<<(unsigned)((PREP_TOTAL + 255) / 256), 256>>>(x, Wq, Wk, Wv, Wo);
    qkv_kernel<<<dim3(8, 32, 3), 256, GEMM_SMEM_BYTES>>>(bq, bk, bv);
    attn_kernel<<<dim3(16, 32), 256, ATTN_SMEM_BYTES>>>();
    proj_kernel<<<dim3(8, 32), 256, GEMM_SMEM_BYTES>>>(bo, out);
}